// round 14
// baseline (speedup 1.0000x reference)
#include <cuda_runtime.h>
#include <cstdint>

#define W      30
#define TT     4096
#define FF     128
#define F4     (FF / 4)            // 32 float4 lanes per row
#define NS     (TT - W + 1)        // 4067 window starts
#define SEG    120                 // outputs per CTA (4 halves of 30)
#define ROWS   (SEG + W)           // 150 staged rows
#define UNITS  (ROWS * 32)         // 4800 16-byte units to stage
#define SMEM_BYTES (ROWS * FF * 4) // 76800 -> 2 CTAs/SM
#define EPSF   1e-4f

__device__ __forceinline__ void cp16(uint32_t saddr, const void* gaddr) {
    asm volatile("cp.async.cg.shared.global [%0], [%1], 16;" :: "r"(saddr), "l"(gaddr));
}
__device__ __forceinline__ void cp_commit() {
    asm volatile("cp.async.commit_group;");
}
template <int N>
__device__ __forceinline__ void cp_wait() {
    asm volatile("cp.async.wait_group %0;" :: "n"(N));
}

// ---- packed f32x2 helpers (FFMA2 path: PTX-only, ptxas won't auto-fuse) ----
__device__ __forceinline__ uint64_t f2pk(float x, float y) {
    uint64_t r; asm("mov.b64 %0, {%1, %2};" : "=l"(r) : "f"(x), "f"(y)); return r;
}
__device__ __forceinline__ float2 f2up(uint64_t p) {
    float2 v; asm("mov.b64 {%0, %1}, %2;" : "=f"(v.x), "=f"(v.y) : "l"(p)); return v;
}
__device__ __forceinline__ uint64_t f2add(uint64_t a, uint64_t b) {
    uint64_t d; asm("add.rn.f32x2 %0, %1, %2;" : "=l"(d) : "l"(a), "l"(b)); return d;
}
__device__ __forceinline__ uint64_t f2mul(uint64_t a, uint64_t b) {
    uint64_t d; asm("mul.rn.f32x2 %0, %1, %2;" : "=l"(d) : "l"(a), "l"(b)); return d;
}
__device__ __forceinline__ uint64_t f2fma(uint64_t a, uint64_t b, uint64_t c) {
    uint64_t d; asm("fma.rn.f32x2 %0, %1, %2, %3;" : "=l"(d) : "l"(a), "l"(b), "l"(c)); return d;
}

__global__ __launch_bounds__(128)
void ts_zscore_kernel(const float* __restrict__ x, float* __restrict__ out)
{
    extern __shared__ float sm[];
    const int fp  = threadIdx.x;        // feature quad 0..31
    const int h   = threadIdx.y;        // half 0..3 (outputs [h*30, h*30+30))
    const int tid = threadIdx.y * F4 + threadIdx.x;
    const int b   = blockIdx.x;

    int k0 = blockIdx.y * SEG;
    if (k0 > NS - SEG) k0 = NS - SEG;   // tail block overlaps prior (same values)

    const uint32_t sbase = (uint32_t)__cvta_generic_to_shared(sm);
    const float* __restrict__ xb = x + (size_t)b * TT * FF;

    // Stage 150 rows (k0 .. k0+149): 4800 16B units over 128 threads.
    // Last staged row may exceed the tensor by one (k0 max = 3947) — clamp;
    // max consumed local row is 148 (= 3947+148 = 4095), so never consumed.
#pragma unroll
    for (int i = 0; i < 38; ++i) {
        const int idx = tid + i * 128;
        if (i < 37 || idx < UNITS) {
            int grow = k0 + (idx >> 5);
            if (grow > TT - 1) grow = TT - 1;
            const float* g = xb + (size_t)grow * FF + ((idx & 31) << 2);
            cp16(sbase + (uint32_t)idx * 16u, g);
        }
    }
    cp_commit();

    // Per-half bases in float4 units.
    const float4* __restrict__ sg = (const float4*)sm + (size_t)(h * W) * F4 + fp;
    float4* __restrict__ op =
        (float4*)out + ((size_t)b * NS + k0 + h * W) * F4 + fp;

    cp_wait<0>();
    __syncthreads();

    const uint64_t invWp  = f2pk( 1.0f / W,  1.0f / W);
    const uint64_t ninvWp = f2pk(-1.0f / W, -1.0f / W);
    const uint64_t neg1p  = f2pk(-1.0f, -1.0f);

    // Prime s,s2 (two packed chains) with local rows 0..28 of this half.
    uint64_t sp0 = f2pk(0.f, 0.f), sp1 = sp0, s2p0 = sp0, s2p1 = sp0;
#pragma unroll
    for (int i = 0; i < W - 1; ++i) {
        const float4 v = sg[i * F4];
        const uint64_t vp0 = f2pk(v.x, v.y);
        const uint64_t vp1 = f2pk(v.z, v.w);
        sp0  = f2add(sp0, vp0);   sp1  = f2add(sp1, vp1);
        s2p0 = f2fma(vp0, vp0, s2p0);
        s2p1 = f2fma(vp1, vp1, s2p1);
    }

#pragma unroll
    for (int u = 0; u < W; ++u) {
        const float4 nv = sg[(u + W - 1) * F4];  // row entering the window
        const uint64_t nvp0 = f2pk(nv.x, nv.y);
        const uint64_t nvp1 = f2pk(nv.z, nv.w);

        const uint64_t ssp0  = f2add(sp0, nvp0);
        const uint64_t ssp1  = f2add(sp1, nvp1);
        const uint64_t ss2p0 = f2fma(nvp0, nvp0, s2p0);
        const uint64_t ss2p1 = f2fma(nvp1, nvp1, s2p1);

        const uint64_t meanp0 = f2mul(ssp0, invWp);
        const uint64_t meanp1 = f2mul(ssp1, invWp);
        const uint64_t varp0  = f2fma(f2mul(ssp0, ninvWp), meanp0, f2mul(ss2p0, invWp));
        const uint64_t varp1  = f2fma(f2mul(ssp1, ninvWp), meanp1, f2mul(ss2p1, invWp));

        const float2 m0 = f2up(meanp0), m1 = f2up(meanp1);
        float2 v0 = f2up(varp0), v1 = f2up(varp1);
        v0.x = fmaxf(v0.x, 1e-12f);  v0.y = fmaxf(v0.y, 1e-12f);
        v1.x = fmaxf(v1.x, 1e-12f);  v1.y = fmaxf(v1.y, 1e-12f);

        // 1/(std+eps) ~= rs*(1-eps*rs), rs = rsqrt(var); rel err ~ eps^2/var.
        float ra, rb, rc, rd;
        asm("rsqrt.approx.f32 %0, %1;" : "=f"(ra) : "f"(v0.x));
        asm("rsqrt.approx.f32 %0, %1;" : "=f"(rb) : "f"(v0.y));
        asm("rsqrt.approx.f32 %0, %1;" : "=f"(rc) : "f"(v1.x));
        asm("rsqrt.approx.f32 %0, %1;" : "=f"(rd) : "f"(v1.y));

        float4 r;
        r.x = (nv.x - m0.x) * ra * fmaf(-EPSF, ra, 1.0f);
        r.y = (nv.y - m0.y) * rb * fmaf(-EPSF, rb, 1.0f);
        r.z = (nv.z - m1.x) * rc * fmaf(-EPSF, rc, 1.0f);
        r.w = (nv.w - m1.y) * rd * fmaf(-EPSF, rd, 1.0f);
        __stcs(op + (size_t)u * F4, r);          // STG.128 streaming store

        const float4 ov = sg[u * F4];            // row leaving the window
        const uint64_t ovp0 = f2pk(ov.x, ov.y);
        const uint64_t ovp1 = f2pk(ov.z, ov.w);
        const uint64_t novp0 = f2mul(ovp0, neg1p);
        const uint64_t novp1 = f2mul(ovp1, neg1p);
        sp0  = f2add(ssp0, novp0);               // s  = ss  - ov
        sp1  = f2add(ssp1, novp1);
        s2p0 = f2fma(ovp0, novp0, ss2p0);        // s2 = ss2 - ov*ov
        s2p1 = f2fma(ovp1, novp1, ss2p1);
    }
}

extern "C" void kernel_launch(void* const* d_in, const int* in_sizes, int n_in,
                              void* d_out, int out_size)
{
    (void)n_in; (void)out_size;
    const float* x = (const float*)d_in[0];
    float* out = (float*)d_out;

    cudaFuncSetAttribute(ts_zscore_kernel,
                         cudaFuncAttributeMaxDynamicSharedMemorySize, SMEM_BYTES);

    const int B = in_sizes[0] / (TT * FF);   // 64 for this problem
    dim3 block(F4, 4);                        // 128 threads
    dim3 grid(B, (NS + SEG - 1) / SEG);       // (64, 34)
    ts_zscore_kernel<<<grid, block, SMEM_BYTES>>>(x, out);
}

// round 15
// speedup vs baseline: 1.0506x; 1.0506x over previous
#include <cuda_runtime.h>
#include <cstdint>

#define W      30
#define TT     4096
#define FF     128
#define F2     (FF / 2)            // 64 float2 lanes per row
#define NS     (TT - W + 1)        // 4067 window starts
#define HS     37                  // outputs per half
#define SEG    (2 * HS)            // 74 outputs per CTA
#define ROWS   104                 // staged rows (>= SEG + W - 1 = 103)
#define UNITS  (ROWS * 32)         // 3328 16-byte units = 26 * 128 (exact)
#define SMEM_BYTES (ROWS * FF * 4) // 53248 -> 4 CTAs/SM
#define EPSF   1e-4f

__device__ __forceinline__ void cp16(uint32_t saddr, const void* gaddr) {
    asm volatile("cp.async.cg.shared.global [%0], [%1], 16;" :: "r"(saddr), "l"(gaddr));
}
__device__ __forceinline__ void cp_commit() {
    asm volatile("cp.async.commit_group;");
}
template <int N>
__device__ __forceinline__ void cp_wait() {
    asm volatile("cp.async.wait_group %0;" :: "n"(N));
}

// ---- packed f32x2 helpers (FFMA2 path: PTX-only, ptxas won't auto-fuse) ----
__device__ __forceinline__ uint64_t f2pk(float x, float y) {
    uint64_t r; asm("mov.b64 %0, {%1, %2};" : "=l"(r) : "f"(x), "f"(y)); return r;
}
__device__ __forceinline__ float2 f2up(uint64_t p) {
    float2 v; asm("mov.b64 {%0, %1}, %2;" : "=f"(v.x), "=f"(v.y) : "l"(p)); return v;
}
__device__ __forceinline__ uint64_t f2add(uint64_t a, uint64_t b) {
    uint64_t d; asm("add.rn.f32x2 %0, %1, %2;" : "=l"(d) : "l"(a), "l"(b)); return d;
}
__device__ __forceinline__ uint64_t f2mul(uint64_t a, uint64_t b) {
    uint64_t d; asm("mul.rn.f32x2 %0, %1, %2;" : "=l"(d) : "l"(a), "l"(b)); return d;
}
__device__ __forceinline__ uint64_t f2fma(uint64_t a, uint64_t b, uint64_t c) {
    uint64_t d; asm("fma.rn.f32x2 %0, %1, %2, %3;" : "=l"(d) : "l"(a), "l"(b), "l"(c)); return d;
}

__global__ __launch_bounds__(128)
void ts_zscore_kernel(const float* __restrict__ x, float* __restrict__ out)
{
    extern __shared__ float sm[];
    const int fp  = threadIdx.x;        // feature pair 0..63
    const int h   = threadIdx.y;        // half 0..1 (outputs [h*HS, h*HS+HS))
    const int tid = threadIdx.y * F2 + threadIdx.x;
    const int b   = blockIdx.x;

    int k0 = blockIdx.y * SEG;
    if (k0 > NS - SEG) k0 = NS - SEG;   // tail block overlaps prior (same values)

    const uint32_t sbase = (uint32_t)__cvta_generic_to_shared(sm);
    const float* __restrict__ xb = x + (size_t)b * TT * FF;

    // Stage 104 rows (k0 .. k0+103): 3328 16B units over 128 threads,
    // exactly 26 rounds (no predicate). Last staged row may exceed the
    // tensor by one (k0 max = 3993 -> row 4096) — clamp; max consumed
    // local row is 102, so the clamped row is never consumed.
#pragma unroll
    for (int i = 0; i < 26; ++i) {
        const int idx = tid + i * 128;
        int grow = k0 + (idx >> 5);
        if (grow > TT - 1) grow = TT - 1;
        const float* g = xb + (size_t)grow * FF + ((idx & 31) << 2);
        cp16(sbase + (uint32_t)idx * 16u, g);
    }
    cp_commit();

    // Per-half bases in float2 units.
    const float2* __restrict__ sg = (const float2*)sm + (size_t)(h * HS) * F2 + fp;
    float2* __restrict__ op =
        (float2*)out + ((size_t)b * NS + k0 + h * HS) * F2 + fp;

    cp_wait<0>();
    __syncthreads();

    const uint64_t invWp  = f2pk( 1.0f / W,  1.0f / W);
    const uint64_t ninvWp = f2pk(-1.0f / W, -1.0f / W);
    const uint64_t neg1p  = f2pk(-1.0f, -1.0f);

    // Prime s,s2 (packed) with local rows 0..28 of this half.
    uint64_t sp = f2pk(0.f, 0.f), s2p = sp;
#pragma unroll
    for (int i = 0; i < W - 1; ++i) {
        const float2 v = sg[i * F2];
        const uint64_t vp = f2pk(v.x, v.y);
        sp  = f2add(sp, vp);
        s2p = f2fma(vp, vp, s2p);
    }

#pragma unroll
    for (int u = 0; u < HS; ++u) {
        const float2 nv = sg[(u + W - 1) * F2];  // row entering the window
        const uint64_t nvp = f2pk(nv.x, nv.y);

        const uint64_t ssp  = f2add(sp, nvp);
        const uint64_t ss2p = f2fma(nvp, nvp, s2p);

        const uint64_t meanp   = f2mul(ssp, invWp);
        const uint64_t nmeanp  = f2mul(ssp, ninvWp);
        const uint64_t meansqp = f2mul(ss2p, invWp);
        const uint64_t varp    = f2fma(nmeanp, meanp, meansqp);

        const float2 mean = f2up(meanp);
        float2 var = f2up(varp);
        var.x = fmaxf(var.x, 1e-12f);
        var.y = fmaxf(var.y, 1e-12f);

        // 1/(std+eps) ~= rs*(1-eps*rs), rs = rsqrt(var); rel err ~ eps^2/var.
        float rsx, rsy;
        asm("rsqrt.approx.f32 %0, %1;" : "=f"(rsx) : "f"(var.x));
        asm("rsqrt.approx.f32 %0, %1;" : "=f"(rsy) : "f"(var.y));

        float2 r;
        r.x = (nv.x - mean.x) * rsx * fmaf(-EPSF, rsx, 1.0f);
        r.y = (nv.y - mean.y) * rsy * fmaf(-EPSF, rsy, 1.0f);
        __stcs(op + (size_t)u * F2, r);          // STG.64 streaming store

        const float2 ov = sg[u * F2];            // row leaving the window
        const uint64_t ovp  = f2pk(ov.x, ov.y);
        const uint64_t novp = f2mul(ovp, neg1p);
        sp  = f2add(ssp, novp);                  // s  = ss  - ov
        s2p = f2fma(ovp, novp, ss2p);            // s2 = ss2 - ov*ov
    }
}

extern "C" void kernel_launch(void* const* d_in, const int* in_sizes, int n_in,
                              void* d_out, int out_size)
{
    (void)n_in; (void)out_size;
    const float* x = (const float*)d_in[0];
    float* out = (float*)d_out;

    cudaFuncSetAttribute(ts_zscore_kernel,
                         cudaFuncAttributeMaxDynamicSharedMemorySize, SMEM_BYTES);

    const int B = in_sizes[0] / (TT * FF);   // 64 for this problem
    dim3 block(F2, 2);                        // 128 threads
    dim3 grid(B, (NS + SEG - 1) / SEG);       // (64, 55) = 3520 CTAs ~ 5.95 waves
    ts_zscore_kernel<<<grid, block, SMEM_BYTES>>>(x, out);
}